// round 5
// baseline (speedup 1.0000x reference)
#include <cuda_runtime.h>
#include <cstdint>

// ---------------- problem constants ----------------
#define BB 64
#define VOC 40
#define EMBD 32
#define L0N 512
#define L1N 1024
#define L2N 2048
#define NSUM (L0N + L1N + L2N)   // 3584
#define LATENT 512
#define STEPS 50
#define START_TOK 39
#define LOGITS_OFF (BB * STEPS)  // 3200

#define GRID 128
#define TPB  512
#define KBLK 32
#define XPAD 66   // smem row stride (uint64 units), even => 16B alignment kept

// ---------------- persistent device state (no allocation allowed) ----------------
__device__ float g_h0[BB * L0N];
__device__ float g_h1[BB * L1N];
__device__ float g_h2[BB * L2N];
__device__ float g_n0[BB * L0N];
__device__ float g_n1[BB * L1N];
__device__ float g_n2[BB * L2N];
__device__ float g_v0[BB * 2 * L0N];
__device__ float g_v1[BB * 2 * L1N];
__device__ float g_v2[BB * 2 * L2N];
__device__ float g_x[BB * EMBD];
__device__ int   g_done[BB];
__device__ float g_scr[4 * 1024 * 1024];   // 16MB split-K partial sums

// grid barrier state (monotonic generation; safe across graph replays)
__device__ unsigned          g_barcnt = 0;
__device__ volatile unsigned g_bargen = 0;

// ---------------- helpers ----------------
__device__ __forceinline__ void ffma2(uint64_t& d, uint64_t a, uint64_t b) {
    asm("fma.rn.f32x2 %0, %1, %2, %0;" : "+l"(d) : "l"(a), "l"(b));
}
__device__ __forceinline__ uint64_t pack2(float lo, float hi) {
    uint64_t r;
    asm("mov.b64 %0, {%1, %2};" : "=l"(r) : "f"(lo), "f"(hi));
    return r;
}
__device__ __forceinline__ void unpack2(uint64_t v, float& lo, float& hi) {
    asm("mov.b64 {%0, %1}, %2;" : "=f"(lo), "=f"(hi) : "l"(v));
}
__device__ __forceinline__ float sigmoidf_(float x) {
    return 1.0f / (1.0f + expf(-x));
}

// all 128 blocks are co-resident (GRID < 148 SMs) -> spin barrier is safe
__device__ __forceinline__ void grid_bar() {
    __syncthreads();
    if (threadIdx.x == 0) {
        unsigned gen = g_bargen;
        __threadfence();
        if (atomicAdd(&g_barcnt, 1u) == GRID - 1) {
            g_barcnt = 0;
            __threadfence();
            g_bargen = gen + 1;
        } else {
            while (g_bargen == gen) { __nanosleep(64); }
            __threadfence();
        }
    }
    __syncthreads();
}

// ---------------- split-K GEMM phase ----------------
// Block tile: 512 cols x 64 rows, K-chunked. Thread: 8 cols (4 pairs) x 8 rows.
// 64 col-threads (c = tid&63) x 8 row-groups (rg = tid>>6).
// Partials -> g_scr[chunk][row][colpair].
// MODE 0: input = concat[x, h];  MODE 1: input = concat[x, r*h] (r = 1st half of v)
template<int IN, int OUT, int NCOL, int TILES, int CHUNKS, int MODE>
__device__ __forceinline__ void gemm_phase(
    const float* __restrict__ W,
    const float* __restrict__ xbuf,
    const float* __restrict__ hbuf,
    const float* __restrict__ vbuf,
    uint64_t* __restrict__ s_x2)   // smem: KBLK * XPAD uint64
{
    constexpr int KTOT = IN + OUT;
    constexpr int KC   = (KTOT + CHUNKS - 1) / CHUNKS;

    const int bid = blockIdx.x;
    if (bid < TILES * CHUNKS) {
        const int tile  = bid % TILES;
        const int chunk = bid / TILES;
        const int k0 = chunk * KC;
        const int k1 = (k0 + KC < KTOT) ? (k0 + KC) : KTOT;
        const int jbase = tile * 512;
        const int tid = threadIdx.x;
        const int c  = tid & 63;   // col-thread: 8 cols
        const int rg = tid >> 6;   // row-group: 8 rows

        uint64_t acc[4][8];
#pragma unroll
        for (int cp = 0; cp < 4; cp++)
#pragma unroll
            for (int r = 0; r < 8; r++) acc[cp][r] = 0ull;

        const float* Wc = W + jbase + c * 8;

        for (int kb = k0; kb < k1; kb += KBLK) {
            const int kt = (k1 - kb < KBLK) ? (k1 - kb) : KBLK;
            __syncthreads();
            // stage inputs: lanes stride over k (coalesced gmem), duplicated pair in smem
            for (int idx = tid; idx < 64 * KBLK; idx += TPB) {
                const int kk  = idx & (KBLK - 1);
                const int row = idx >> 5;
                if (kk < kt) {
                    const int kg = kb + kk;
                    float val;
                    if (kg < IN) {
                        val = xbuf[row * IN + kg];
                    } else {
                        const int q = kg - IN;
                        const float hv = hbuf[row * OUT + q];
                        if (MODE == 1)
                            val = vbuf[row * (2 * OUT) + q] * hv;
                        else
                            val = hv;
                    }
                    s_x2[kk * XPAD + row] = pack2(val, val);
                }
            }
            __syncthreads();

            const float* wrow = Wc + (size_t)kb * NCOL;
#pragma unroll 2
            for (int kk = 0; kk < kt; kk++) {
                const ulonglong2 wa  = *reinterpret_cast<const ulonglong2*>(wrow);
                const ulonglong2 wb2 = *reinterpret_cast<const ulonglong2*>(wrow + 4);
                const uint64_t* xr = s_x2 + kk * XPAD + (rg << 3);
                const ulonglong2 x01 = *reinterpret_cast<const ulonglong2*>(xr);
                const ulonglong2 x23 = *reinterpret_cast<const ulonglong2*>(xr + 2);
                const ulonglong2 x45 = *reinterpret_cast<const ulonglong2*>(xr + 4);
                const ulonglong2 x67 = *reinterpret_cast<const ulonglong2*>(xr + 6);
                const uint64_t xd[8] = {x01.x, x01.y, x23.x, x23.y,
                                        x45.x, x45.y, x67.x, x67.y};
#pragma unroll
                for (int r = 0; r < 8; r++) {
                    ffma2(acc[0][r], wa.x,  xd[r]);
                    ffma2(acc[1][r], wa.y,  xd[r]);
                    ffma2(acc[2][r], wb2.x, xd[r]);
                    ffma2(acc[3][r], wb2.y, xd[r]);
                }
                wrow += NCOL;
            }
        }

        // epilogue: partials to scratch (uint64 = col-pair)
        uint64_t* scr = reinterpret_cast<uint64_t*>(g_scr);
#pragma unroll
        for (int r = 0; r < 8; r++) {
            const int row = (rg << 3) + r;
            uint64_t* dst = scr + (size_t)(chunk * 64 + row) * (NCOL / 2)
                                + (jbase >> 1) + (c << 2);
#pragma unroll
            for (int cp = 0; cp < 4; cp++) dst[cp] = acc[cp][r];
        }
    }
    grid_bar();
}

// ---------------- reduce + activation phases ----------------
template<int OUT, int CHUNKS>
__device__ __forceinline__ void reduce_gates(const float* __restrict__ bg,
                                             float* __restrict__ v)
{
    const int NP = 64 * OUT;   // col-pairs (NCOL/2 = OUT)
    const uint64_t* scr = reinterpret_cast<const uint64_t*>(g_scr);
    for (int p = blockIdx.x * TPB + threadIdx.x; p < NP; p += GRID * TPB) {
        const int row = p / OUT;
        const int jp  = p - row * OUT;
        float s0 = 0.f, s1 = 0.f;
#pragma unroll 8
        for (int ch = 0; ch < CHUNKS; ch++) {
            float a, b;
            unpack2(scr[(size_t)(ch * 64 + row) * OUT + jp], a, b);
            s0 += a; s1 += b;
        }
        const int j = jp * 2;
        v[row * (2 * OUT) + j]     = sigmoidf_(s0 + bg[j]);
        v[row * (2 * OUT) + j + 1] = sigmoidf_(s1 + bg[j + 1]);
    }
    grid_bar();
}

template<int OUT, int CHUNKS>
__device__ __forceinline__ void reduce_cand(const float* __restrict__ bc,
                                            const float* __restrict__ v,
                                            const float* __restrict__ h,
                                            float* __restrict__ n)
{
    constexpr int HP = OUT / 2;
    const int NP = 64 * HP;
    const uint64_t* scr = reinterpret_cast<const uint64_t*>(g_scr);
    for (int p = blockIdx.x * TPB + threadIdx.x; p < NP; p += GRID * TPB) {
        const int row = p / HP;
        const int jp  = p - row * HP;
        float s0 = 0.f, s1 = 0.f;
#pragma unroll 8
        for (int ch = 0; ch < CHUNKS; ch++) {
            float a, b;
            unpack2(scr[(size_t)(ch * 64 + row) * HP + jp], a, b);
            s0 += a; s1 += b;
        }
        const int j = jp * 2;
#pragma unroll
        for (int t = 0; t < 2; t++) {
            const float cv = tanhf(((t == 0) ? s0 : s1) + bc[j + t]);
            const float z  = v[row * (2 * OUT) + OUT + j + t];
            const float hv = h[row * OUT + j + t];
            n[row * OUT + j + t] = z * hv + (1.0f - z) * cv;
        }
    }
    grid_bar();
}

__device__ __forceinline__ void reduce_dense(const float* __restrict__ db)
{
    constexpr int HP = NSUM / 2;   // 1792
    const int NP = 64 * HP;
    const uint64_t* scr = reinterpret_cast<const uint64_t*>(g_scr);
    for (int p = blockIdx.x * TPB + threadIdx.x; p < NP; p += GRID * TPB) {
        const int row = p / HP;
        const int jp  = p - row * HP;
        float s0 = 0.f, s1 = 0.f;
#pragma unroll 6
        for (int ch = 0; ch < 18; ch++) {
            float a, b;
            unpack2(scr[(size_t)(ch * 64 + row) * HP + jp], a, b);
            s0 += a; s1 += b;
        }
        const int j = jp * 2;
        const float y0 = s0 + db[j];
        const float y1 = s1 + db[j + 1];
        if (j < L0N) {
            g_h0[row * L0N + j] = y0; g_h0[row * L0N + j + 1] = y1;
        } else if (j < L0N + L1N) {
            g_h1[row * L1N + (j - L0N)] = y0; g_h1[row * L1N + (j - L0N) + 1] = y1;
        } else {
            g_h2[row * L2N + (j - L0N - L1N)] = y0; g_h2[row * L2N + (j - L0N - L1N) + 1] = y1;
        }
    }
    grid_bar();
}

// ---------------- decode phase ----------------
__device__ __forceinline__ void decode_phase(const float* __restrict__ decW,
                                             const float* __restrict__ emb,
                                             float* __restrict__ out, int step)
{
    if (blockIdx.x < BB) {
        __shared__ float s_logit[VOC];
        __shared__ int s_idx, s_d0;
        const int b    = blockIdx.x;
        const int tid  = threadIdx.x;
        const int w    = tid >> 5;      // 16 warps
        const int lane = tid & 31;

        if (w < 8) {   // 8 warps x 5 logit cols
            float acc[5];
#pragma unroll
            for (int jj = 0; jj < 5; jj++) acc[jj] = 0.0f;

            const float* n2row = g_n2 + b * L2N;
            for (int k = lane; k < L2N; k += 32) {
                const float xv = n2row[k];
                const float* wr = decW + k * VOC + w * 5;
#pragma unroll
                for (int jj = 0; jj < 5; jj++) acc[jj] += xv * wr[jj];
            }
#pragma unroll
            for (int jj = 0; jj < 5; jj++) {
                float s = acc[jj];
#pragma unroll
                for (int off = 16; off > 0; off >>= 1)
                    s += __shfl_down_sync(0xffffffffu, s, off);
                if (lane == 0) s_logit[w * 5 + jj] = s;
            }
        }
        __syncthreads();

        if (tid == 0) {
            const int d0 = g_done[b];
            float best = s_logit[0];
            int bi = 0;
            for (int jj = 1; jj < VOC; jj++) {
                const float lv = s_logit[jj];
                if (lv > best) { best = lv; bi = jj; }   // first-max on ties
            }
            s_idx = bi;
            s_d0  = d0;
            out[b * STEPS + step] = (float)(d0 ? 0 : bi);   // STOP_TOK == 0
            g_done[b] = d0 | (bi == 0);
        }
        __syncthreads();

        const int d0  = s_d0;
        const int idx = s_idx;

        float* lo = out + LOGITS_OFF + (b * STEPS + step) * VOC;
        for (int jj = tid; jj < VOC; jj += TPB)
            lo[jj] = d0 ? 0.0f : s_logit[jj];

        if (!d0) {
            for (int q = tid; q < L0N; q += TPB) g_h0[b * L0N + q] = g_n0[b * L0N + q];
            for (int q = tid; q < L1N; q += TPB) g_h1[b * L1N + q] = g_n1[b * L1N + q];
            for (int q = tid; q < L2N; q += TPB) g_h2[b * L2N + q] = g_n2[b * L2N + q];
            if (tid < EMBD) g_x[b * EMBD + tid] = emb[idx * EMBD + tid];
        }
    }
    grid_bar();
}

// ---------------- the single persistent kernel ----------------
__global__ void __launch_bounds__(TPB, 1) decoder_kernel(
    const float* __restrict__ iv,   const float* __restrict__ emb,
    const float* __restrict__ dW,   const float* __restrict__ db,
    const float* __restrict__ decW,
    const float* __restrict__ Kg0, const float* __restrict__ bg0,
    const float* __restrict__ Kc0, const float* __restrict__ bc0,
    const float* __restrict__ Kg1, const float* __restrict__ bg1,
    const float* __restrict__ Kc1, const float* __restrict__ bc1,
    const float* __restrict__ Kg2, const float* __restrict__ bg2,
    const float* __restrict__ Kc2, const float* __restrict__ bc2,
    float* __restrict__ out)
{
    __shared__ __align__(16) uint64_t s_x2[KBLK * XPAD];

    // init x / done (blocks 126,127 idle during the 126-block dense gemm)
    if (blockIdx.x == 126) {
        for (int i = threadIdx.x; i < BB * EMBD; i += TPB)
            g_x[i] = emb[START_TOK * EMBD + (i & (EMBD - 1))];
        if (threadIdx.x < BB) g_done[threadIdx.x] = 0;
    }

    // initial hidden states: y = iv @ dense_W + dense_b
    gemm_phase<LATENT, 0, NSUM, 7, 18, 0>(dW, iv, nullptr, nullptr, s_x2);
    reduce_dense(db);

    for (int s = 0; s < STEPS; s++) {
        gemm_phase<EMBD, L0N, 2 * L0N, 2, 32, 0>(Kg0, g_x,  g_h0, nullptr, s_x2);
        reduce_gates<L0N, 32>(bg0, g_v0);
        gemm_phase<EMBD, L0N, L0N,     1, 32, 1>(Kc0, g_x,  g_h0, g_v0,   s_x2);
        reduce_cand<L0N, 32>(bc0, g_v0, g_h0, g_n0);

        gemm_phase<L0N,  L1N, 2 * L1N, 4, 32, 0>(Kg1, g_n0, g_h1, nullptr, s_x2);
        reduce_gates<L1N, 32>(bg1, g_v1);
        gemm_phase<L0N,  L1N, L1N,     2, 64, 1>(Kc1, g_n0, g_h1, g_v1,   s_x2);
        reduce_cand<L1N, 64>(bc1, g_v1, g_h1, g_n1);

        gemm_phase<L1N,  L2N, 2 * L2N, 8, 16, 0>(Kg2, g_n1, g_h2, nullptr, s_x2);
        reduce_gates<L2N, 16>(bg2, g_v2);
        gemm_phase<L1N,  L2N, L2N,     4, 32, 1>(Kc2, g_n1, g_h2, g_v2,   s_x2);
        reduce_cand<L2N, 32>(bc2, g_v2, g_h2, g_n2);

        decode_phase(decW, emb, out, s);
    }
}

// ---------------- launch ----------------
extern "C" void kernel_launch(void* const* d_in, const int* in_sizes, int n_in,
                              void* d_out, int out_size)
{
    const float* iv   = (const float*)d_in[0];
    const float* emb  = (const float*)d_in[1];
    const float* dW   = (const float*)d_in[2];
    const float* db   = (const float*)d_in[3];
    const float* decW = (const float*)d_in[4];
    const float* Kg0  = (const float*)d_in[5];
    const float* bg0  = (const float*)d_in[6];
    const float* Kc0  = (const float*)d_in[7];
    const float* bc0  = (const float*)d_in[8];
    const float* Kg1  = (const float*)d_in[9];
    const float* bg1  = (const float*)d_in[10];
    const float* Kc1  = (const float*)d_in[11];
    const float* bc1  = (const float*)d_in[12];
    const float* Kg2  = (const float*)d_in[13];
    const float* bg2  = (const float*)d_in[14];
    const float* Kc2  = (const float*)d_in[15];
    const float* bc2  = (const float*)d_in[16];
    float* out = (float*)d_out;

    decoder_kernel<<<GRID, TPB>>>(iv, emb, dW, db, decW,
                                  Kg0, bg0, Kc0, bc0,
                                  Kg1, bg1, Kc1, bc1,
                                  Kg2, bg2, Kc2, bc2, out);
}

// round 6
// speedup vs baseline: 1.1154x; 1.1154x over previous
#include <cuda_runtime.h>
#include <cstdint>

// ---------------- problem constants ----------------
#define BB 64
#define VOC 40
#define EMBD 32
#define L0N 512
#define L1N 1024
#define L2N 2048
#define NSUM (L0N + L1N + L2N)   // 3584
#define LATENT 512
#define STEPS 50
#define START_TOK 39
#define LOGITS_OFF (BB * STEPS)  // 3200

#define GRID 128
#define TPB  512
#define KBLK 32
#define XPAD 66   // smem row stride (uint64 units), even => 16B alignment kept

// ---------------- persistent device state (no allocation allowed) ----------------
__device__ float g_h0[BB * L0N];
__device__ float g_h1[BB * L1N];
__device__ float g_h2[BB * L2N];
__device__ float g_n0[BB * L0N];
__device__ float g_n1[BB * L1N];
__device__ float g_n2[BB * L2N];
__device__ float g_v0[BB * 2 * L0N];
__device__ float g_v1[BB * 2 * L1N];
__device__ float g_v2[BB * 2 * L2N];
__device__ float g_x[BB * EMBD];
__device__ int   g_done[BB];
__device__ float g_scr[4 * 1024 * 1024];   // 16MB split-K partial sums

// grid barrier state (monotonic generation; safe across graph replays)
__device__ unsigned          g_barcnt = 0;
__device__ volatile unsigned g_bargen = 0;

// ---------------- helpers ----------------
__device__ __forceinline__ void ffma2(uint64_t& d, uint64_t a, uint64_t b) {
    asm("fma.rn.f32x2 %0, %1, %2, %0;" : "+l"(d) : "l"(a), "l"(b));
}
__device__ __forceinline__ uint64_t pack2(float lo, float hi) {
    uint64_t r;
    asm("mov.b64 %0, {%1, %2};" : "=l"(r) : "f"(lo), "f"(hi));
    return r;
}
__device__ __forceinline__ void unpack2(uint64_t v, float& lo, float& hi) {
    asm("mov.b64 {%0, %1}, %2;" : "=f"(lo), "=f"(hi) : "l"(v));
}
__device__ __forceinline__ float sigmoidf_(float x) {
    return 1.0f / (1.0f + expf(-x));
}

// all 128 blocks are co-resident (GRID < 148 SMs) -> spin barrier is safe
__device__ __forceinline__ void grid_bar() {
    __syncthreads();
    if (threadIdx.x == 0) {
        unsigned gen = g_bargen;
        __threadfence();
        if (atomicAdd(&g_barcnt, 1u) == GRID - 1) {
            g_barcnt = 0;
            __threadfence();
            g_bargen = gen + 1;
        } else {
            while (g_bargen == gen) { __nanosleep(64); }
            __threadfence();
        }
    }
    __syncthreads();
}

// ---------------- split-K GEMM phase ----------------
// Block tile: 512 cols x 64 rows, K-chunked.
// Thread: 4 cols (2 pairs) x 16 rows.  128 col-threads (c = tid&127) x 4 row-groups.
// Weight loads register double-buffered (prefetch distance 1) to hide L2 latency.
// Partials -> g_scr[chunk][row][colpair].
// MODE 0: input = concat[x, h];  MODE 1: input = concat[x, r*h] (r = 1st half of v)
template<int IN, int OUT, int NCOL, int TILES, int CHUNKS, int MODE>
__device__ __forceinline__ void gemm_phase(
    const float* __restrict__ W,
    const float* __restrict__ xbuf,
    const float* __restrict__ hbuf,
    const float* __restrict__ vbuf,
    uint64_t* __restrict__ s_x2)   // smem: KBLK * XPAD uint64
{
    constexpr int KTOT = IN + OUT;
    constexpr int KC   = (KTOT + CHUNKS - 1) / CHUNKS;

    const int bid = blockIdx.x;
    if (bid < TILES * CHUNKS) {
        const int tile  = bid % TILES;
        const int chunk = bid / TILES;
        const int k0 = chunk * KC;
        const int k1 = (k0 + KC < KTOT) ? (k0 + KC) : KTOT;
        const int jbase = tile * 512;
        const int tid = threadIdx.x;
        const int c  = tid & 127;  // col-thread: 4 cols (2 pairs)
        const int rg = tid >> 7;   // row-group: 16 rows

        uint64_t acc[2][16];
#pragma unroll
        for (int cp = 0; cp < 2; cp++)
#pragma unroll
            for (int r = 0; r < 16; r++) acc[cp][r] = 0ull;

        const float* Wc = W + jbase + c * 4;

        for (int kb = k0; kb < k1; kb += KBLK) {
            const int kt = (k1 - kb < KBLK) ? (k1 - kb) : KBLK;
            __syncthreads();
            // stage inputs: lanes stride over k (coalesced gmem), duplicated pair in smem
            for (int idx = tid; idx < 64 * KBLK; idx += TPB) {
                const int kk  = idx & (KBLK - 1);
                const int row = idx >> 5;
                if (kk < kt) {
                    const int kg = kb + kk;
                    float val;
                    if (kg < IN) {
                        val = xbuf[row * IN + kg];
                    } else {
                        const int q = kg - IN;
                        const float hv = hbuf[row * OUT + q];
                        if (MODE == 1)
                            val = vbuf[row * (2 * OUT) + q] * hv;
                        else
                            val = hv;
                    }
                    s_x2[kk * XPAD + row] = pack2(val, val);
                }
            }
            __syncthreads();

            const float* wrow = Wc + (size_t)kb * NCOL;
            ulonglong2 wcur = *reinterpret_cast<const ulonglong2*>(wrow);
#pragma unroll 2
            for (int kk = 0; kk < kt; kk++) {
                // prefetch next k's weights while computing this k
                ulonglong2 wnext = wcur;
                if (kk + 1 < kt)
                    wnext = *reinterpret_cast<const ulonglong2*>(wrow + NCOL);

                const uint64_t* xr = s_x2 + kk * XPAD + (rg << 4);
#pragma unroll
                for (int rr = 0; rr < 8; rr++) {
                    const ulonglong2 xp = *reinterpret_cast<const ulonglong2*>(xr + 2 * rr);
                    ffma2(acc[0][2 * rr],     wcur.x, xp.x);
                    ffma2(acc[1][2 * rr],     wcur.y, xp.x);
                    ffma2(acc[0][2 * rr + 1], wcur.x, xp.y);
                    ffma2(acc[1][2 * rr + 1], wcur.y, xp.y);
                }
                wcur = wnext;
                wrow += NCOL;
            }
        }

        // epilogue: partials to scratch (uint64 = col-pair)
        uint64_t* scr = reinterpret_cast<uint64_t*>(g_scr);
#pragma unroll
        for (int r = 0; r < 16; r++) {
            const int row = (rg << 4) + r;
            uint64_t* dst = scr + (size_t)(chunk * 64 + row) * (NCOL / 2)
                                + (jbase >> 1) + (c << 1);
            dst[0] = acc[0][r];
            dst[1] = acc[1][r];
        }
    }
    grid_bar();
}

// ---------------- reduce + activation phases ----------------
template<int OUT, int CHUNKS>
__device__ __forceinline__ void reduce_gates(const float* __restrict__ bg,
                                             float* __restrict__ v)
{
    const int NP = 64 * OUT;   // col-pairs (NCOL/2 = OUT)
    const uint64_t* scr = reinterpret_cast<const uint64_t*>(g_scr);
    for (int p = blockIdx.x * TPB + threadIdx.x; p < NP; p += GRID * TPB) {
        const int row = p / OUT;
        const int jp  = p - row * OUT;
        float s0 = 0.f, s1 = 0.f;
#pragma unroll 8
        for (int ch = 0; ch < CHUNKS; ch++) {
            float a, b;
            unpack2(scr[(size_t)(ch * 64 + row) * OUT + jp], a, b);
            s0 += a; s1 += b;
        }
        const int j = jp * 2;
        v[row * (2 * OUT) + j]     = sigmoidf_(s0 + bg[j]);
        v[row * (2 * OUT) + j + 1] = sigmoidf_(s1 + bg[j + 1]);
    }
    grid_bar();
}

template<int OUT, int CHUNKS>
__device__ __forceinline__ void reduce_cand(const float* __restrict__ bc,
                                            const float* __restrict__ v,
                                            const float* __restrict__ h,
                                            float* __restrict__ n)
{
    constexpr int HP = OUT / 2;
    const int NP = 64 * HP;
    const uint64_t* scr = reinterpret_cast<const uint64_t*>(g_scr);
    for (int p = blockIdx.x * TPB + threadIdx.x; p < NP; p += GRID * TPB) {
        const int row = p / HP;
        const int jp  = p - row * HP;
        float s0 = 0.f, s1 = 0.f;
#pragma unroll 8
        for (int ch = 0; ch < CHUNKS; ch++) {
            float a, b;
            unpack2(scr[(size_t)(ch * 64 + row) * HP + jp], a, b);
            s0 += a; s1 += b;
        }
        const int j = jp * 2;
#pragma unroll
        for (int t = 0; t < 2; t++) {
            const float cv = tanhf(((t == 0) ? s0 : s1) + bc[j + t]);
            const float z  = v[row * (2 * OUT) + OUT + j + t];
            const float hv = h[row * OUT + j + t];
            n[row * OUT + j + t] = z * hv + (1.0f - z) * cv;
        }
    }
    grid_bar();
}

__device__ __forceinline__ void reduce_dense(const float* __restrict__ db)
{
    constexpr int HP = NSUM / 2;   // 1792
    const int NP = 64 * HP;
    const uint64_t* scr = reinterpret_cast<const uint64_t*>(g_scr);
    for (int p = blockIdx.x * TPB + threadIdx.x; p < NP; p += GRID * TPB) {
        const int row = p / HP;
        const int jp  = p - row * HP;
        float s0 = 0.f, s1 = 0.f;
#pragma unroll 6
        for (int ch = 0; ch < 18; ch++) {
            float a, b;
            unpack2(scr[(size_t)(ch * 64 + row) * HP + jp], a, b);
            s0 += a; s1 += b;
        }
        const int j = jp * 2;
        const float y0 = s0 + db[j];
        const float y1 = s1 + db[j + 1];
        if (j < L0N) {
            g_h0[row * L0N + j] = y0; g_h0[row * L0N + j + 1] = y1;
        } else if (j < L0N + L1N) {
            g_h1[row * L1N + (j - L0N)] = y0; g_h1[row * L1N + (j - L0N) + 1] = y1;
        } else {
            g_h2[row * L2N + (j - L0N - L1N)] = y0; g_h2[row * L2N + (j - L0N - L1N) + 1] = y1;
        }
    }
    grid_bar();
}

// ---------------- decode phase ----------------
__device__ __forceinline__ void decode_phase(const float* __restrict__ decW,
                                             const float* __restrict__ emb,
                                             float* __restrict__ out, int step)
{
    if (blockIdx.x < BB) {
        __shared__ float s_logit[VOC];
        __shared__ int s_idx, s_d0;
        const int b    = blockIdx.x;
        const int tid  = threadIdx.x;
        const int w    = tid >> 5;      // 16 warps
        const int lane = tid & 31;

        if (w < 8) {   // 8 warps x 5 logit cols
            float acc[5];
#pragma unroll
            for (int jj = 0; jj < 5; jj++) acc[jj] = 0.0f;

            const float* n2row = g_n2 + b * L2N;
            for (int k = lane; k < L2N; k += 32) {
                const float xv = n2row[k];
                const float* wr = decW + k * VOC + w * 5;
#pragma unroll
                for (int jj = 0; jj < 5; jj++) acc[jj] += xv * wr[jj];
            }
#pragma unroll
            for (int jj = 0; jj < 5; jj++) {
                float s = acc[jj];
#pragma unroll
                for (int off = 16; off > 0; off >>= 1)
                    s += __shfl_down_sync(0xffffffffu, s, off);
                if (lane == 0) s_logit[w * 5 + jj] = s;
            }
        }
        __syncthreads();

        if (tid == 0) {
            const int d0 = g_done[b];
            float best = s_logit[0];
            int bi = 0;
            for (int jj = 1; jj < VOC; jj++) {
                const float lv = s_logit[jj];
                if (lv > best) { best = lv; bi = jj; }   // first-max on ties
            }
            s_idx = bi;
            s_d0  = d0;
            out[b * STEPS + step] = (float)(d0 ? 0 : bi);   // STOP_TOK == 0
            g_done[b] = d0 | (bi == 0);
        }
        __syncthreads();

        const int d0  = s_d0;
        const int idx = s_idx;

        float* lo = out + LOGITS_OFF + (b * STEPS + step) * VOC;
        for (int jj = tid; jj < VOC; jj += TPB)
            lo[jj] = d0 ? 0.0f : s_logit[jj];

        if (!d0) {
            for (int q = tid; q < L0N; q += TPB) g_h0[b * L0N + q] = g_n0[b * L0N + q];
            for (int q = tid; q < L1N; q += TPB) g_h1[b * L1N + q] = g_n1[b * L1N + q];
            for (int q = tid; q < L2N; q += TPB) g_h2[b * L2N + q] = g_n2[b * L2N + q];
            if (tid < EMBD) g_x[b * EMBD + tid] = emb[idx * EMBD + tid];
        }
    }
    grid_bar();
}

// ---------------- the single persistent kernel ----------------
__global__ void __launch_bounds__(TPB, 1) decoder_kernel(
    const float* __restrict__ iv,   const float* __restrict__ emb,
    const float* __restrict__ dW,   const float* __restrict__ db,
    const float* __restrict__ decW,
    const float* __restrict__ Kg0, const float* __restrict__ bg0,
    const float* __restrict__ Kc0, const float* __restrict__ bc0,
    const float* __restrict__ Kg1, const float* __restrict__ bg1,
    const float* __restrict__ Kc1, const float* __restrict__ bc1,
    const float* __restrict__ Kg2, const float* __restrict__ bg2,
    const float* __restrict__ Kc2, const float* __restrict__ bc2,
    float* __restrict__ out)
{
    __shared__ __align__(16) uint64_t s_x2[KBLK * XPAD];

    // init x / done (blocks 126,127 idle during the 126-block dense gemm)
    if (blockIdx.x == 126) {
        for (int i = threadIdx.x; i < BB * EMBD; i += TPB)
            g_x[i] = emb[START_TOK * EMBD + (i & (EMBD - 1))];
        if (threadIdx.x < BB) g_done[threadIdx.x] = 0;
    }

    // initial hidden states: y = iv @ dense_W + dense_b
    gemm_phase<LATENT, 0, NSUM, 7, 18, 0>(dW, iv, nullptr, nullptr, s_x2);
    reduce_dense(db);

    for (int s = 0; s < STEPS; s++) {
        gemm_phase<EMBD, L0N, 2 * L0N, 2, 32, 0>(Kg0, g_x,  g_h0, nullptr, s_x2);
        reduce_gates<L0N, 32>(bg0, g_v0);
        gemm_phase<EMBD, L0N, L0N,     1, 64, 1>(Kc0, g_x,  g_h0, g_v0,   s_x2);
        reduce_cand<L0N, 64>(bc0, g_v0, g_h0, g_n0);

        gemm_phase<L0N,  L1N, 2 * L1N, 4, 32, 0>(Kg1, g_n0, g_h1, nullptr, s_x2);
        reduce_gates<L1N, 32>(bg1, g_v1);
        gemm_phase<L0N,  L1N, L1N,     2, 64, 1>(Kc1, g_n0, g_h1, g_v1,   s_x2);
        reduce_cand<L1N, 64>(bc1, g_v1, g_h1, g_n1);

        gemm_phase<L1N,  L2N, 2 * L2N, 8, 16, 0>(Kg2, g_n1, g_h2, nullptr, s_x2);
        reduce_gates<L2N, 16>(bg2, g_v2);
        gemm_phase<L1N,  L2N, L2N,     4, 32, 1>(Kc2, g_n1, g_h2, g_v2,   s_x2);
        reduce_cand<L2N, 32>(bc2, g_v2, g_h2, g_n2);

        decode_phase(decW, emb, out, s);
    }
}

// ---------------- launch ----------------
extern "C" void kernel_launch(void* const* d_in, const int* in_sizes, int n_in,
                              void* d_out, int out_size)
{
    const float* iv   = (const float*)d_in[0];
    const float* emb  = (const float*)d_in[1];
    const float* dW   = (const float*)d_in[2];
    const float* db   = (const float*)d_in[3];
    const float* decW = (const float*)d_in[4];
    const float* Kg0  = (const float*)d_in[5];
    const float* bg0  = (const float*)d_in[6];
    const float* Kc0  = (const float*)d_in[7];
    const float* bc0  = (const float*)d_in[8];
    const float* Kg1  = (const float*)d_in[9];
    const float* bg1  = (const float*)d_in[10];
    const float* Kc1  = (const float*)d_in[11];
    const float* bc1  = (const float*)d_in[12];
    const float* Kg2  = (const float*)d_in[13];
    const float* bg2  = (const float*)d_in[14];
    const float* Kc2  = (const float*)d_in[15];
    const float* bc2  = (const float*)d_in[16];
    float* out = (float*)d_out;

    decoder_kernel<<<GRID, TPB>>>(iv, emb, dW, db, decW,
                                  Kg0, bg0, Kc0, bc0,
                                  Kg1, bg1, Kc1, bc1,
                                  Kg2, bg2, Kc2, bc2, out);
}